// round 10
// baseline (speedup 1.0000x reference)
#include <cuda_runtime.h>
#include <cuda_fp16.h>
#include <cstdint>

#define NN 256
#define NT 2048
#define NF 128

__device__ __half g_adj16[NN * NN];   // rownorm(adj+I), fp16, [m][k]

__device__ __forceinline__ uint32_t smem_u32(const void* p) {
    uint32_t a;
    asm("{ .reg .u64 t; cvta.to.shared.u64 t, %1; cvt.u32.u64 %0, t; }" : "=r"(a) : "l"(p));
    return a;
}
__device__ __forceinline__ uint32_t packh2(float x, float y) {
    __half2 h = __floats2half2_rn(x, y);
    return *reinterpret_cast<uint32_t*>(&h);
}
#define CP_ASYNC16(dst, src) \
    asm volatile("cp.async.cg.shared.global [%0], [%1], 16;" :: "r"(dst), "l"(src) : "memory")
#define CP_COMMIT() asm volatile("cp.async.commit_group;" ::: "memory")
#define CP_WAIT0()  asm volatile("cp.async.wait_group 0;" ::: "memory")

// ---------------------------------------------------------------------------
__global__ void prep_kernel(const float* __restrict__ adj) {
    __shared__ float red[256];
    int m = blockIdx.x, j = threadIdx.x;
    float v = adj[m * NN + j] + (j == m ? 1.0f : 0.0f);
    red[j] = v;
    __syncthreads();
#pragma unroll
    for (int off = 128; off > 0; off >>= 1) {
        if (j < off) red[j] += red[j + off];
        __syncthreads();
    }
    g_adj16[m * NN + j] = __float2half_rn(v / red[0]);
}

// ---------------------------------------------------------------------------
// Fused GCN, 4 __syncthreads per CTA. One CTA per t, 512 threads = 16 warps
// (4m x 4n), warp tile 64x32, m16n8k16.
//
// smem (196 KB dynamic):
//   SXW [0,     65536):  xw slab fp16, 256 rows x 256B, XOR swizzle
//   BIG [65536, 200704):
//     phase 1: XSTG = BIG          : X_t fp16, 256 rows x 272B (LDSM-clean)
//              SW   = BIG + 69632  : W fp16, 128 rows x 256B, XOR swizzle
//     phase 2: ADJ  = BIG          : adj fp16, 256 rows x 528B (LDSM-clean)
//              (overwrites XSTG+SW after phase-1 seal)
// ---------------------------------------------------------------------------
#define SXW_OFF  0
#define BIG_OFF  65536
#define XSTR     272
#define SW_REL   69632
#define ASTR     528
#define SMEM_TOT 200704

__global__ void __launch_bounds__(512, 1)
fused_gcn(const float* __restrict__ X, const float* __restrict__ W,
          float* __restrict__ out, const float* __restrict__ bias)
{
    extern __shared__ __align__(128) char smem[];
    const uint32_t base = smem_u32(smem);
    const uint32_t SXW  = base + SXW_OFF;
    const uint32_t XSTG = base + BIG_OFF;
    const uint32_t SW   = base + BIG_OFF + SW_REL;
    const uint32_t ADJ  = base + BIG_OFF;

    const int t    = blockIdx.x;
    const int tid  = threadIdx.x;
    const int warp = tid >> 5;
    const int lane = tid & 31;
    const int lr   = lane & 15, lh = lane >> 4;
    const int grp  = lane >> 2, tg = lane & 3;
    const int warp_m = (warp & 3) * 64;
    const int warp_n = (warp >> 2) * 32;

    float acc[4][4][4];

    auto zero_acc = [&] {
#pragma unroll
        for (int i = 0; i < 4; i++)
#pragma unroll
            for (int j = 0; j < 4; j++)
#pragma unroll
                for (int r = 0; r < 4; r++) acc[i][j][r] = 0.0f;
    };
    auto sts16 = [](uint32_t addr, uint4 v) {
        asm volatile("st.shared.v4.b32 [%0], {%1,%2,%3,%4};"
                     :: "r"(addr), "r"(v.x), "r"(v.y), "r"(v.z), "r"(v.w) : "memory");
    };

    // ============ prologue: X_t (full K) + W -> smem, one barrier ============
    // X: 4096 16B-units; 8 per thread, two waves of 4 for bounded reg pressure
#pragma unroll
    for (int w2 = 0; w2 < 2; w2++) {
        float4 v[4][2];
#pragma unroll
        for (int i = 0; i < 4; i++) {
            int idx = tid + (w2 * 4 + i) * 512;
            int row = idx >> 4, seg = idx & 15;
            const float4* src = (const float4*)(X + ((size_t)row * NT + t) * NF + seg * 8);
            v[i][0] = src[0];
            v[i][1] = src[1];
        }
#pragma unroll
        for (int i = 0; i < 4; i++) {
            int idx = tid + (w2 * 4 + i) * 512;
            int row = idx >> 4, seg = idx & 15;
            uint4 u;
            u.x = packh2(v[i][0].x, v[i][0].y); u.y = packh2(v[i][0].z, v[i][0].w);
            u.z = packh2(v[i][1].x, v[i][1].y); u.w = packh2(v[i][1].z, v[i][1].w);
            sts16(XSTG + row * XSTR + seg * 16, u);
        }
    }
    // W -> SW (swizzled for LDSM.trans)
#pragma unroll
    for (int p = 0; p < 4; p++) {
        int u = tid + p * 512;
        int row = u >> 4, seg = u & 15;
        const float4* src = (const float4*)(W + row * NF + seg * 8);
        float4 v0 = src[0], v1 = src[1];
        uint4 w;
        w.x = packh2(v0.x, v0.y); w.y = packh2(v0.z, v0.w);
        w.z = packh2(v1.x, v1.y); w.w = packh2(v1.z, v1.w);
        sts16(SW + row * 256 + ((seg * 16) ^ ((row & 7) << 4)), w);
    }
    zero_acc();
    __syncthreads();                                   // barrier 1

    // ============ phase 1: xw = X_t @ W, 8 k16 steps, no barriers ============
#pragma unroll
    for (int st = 0; st < 8; st++) {
        uint32_t a[4][4];
#pragma unroll
        for (int fm = 0; fm < 4; fm++) {
            uint32_t ad = XSTG + (warp_m + fm * 16 + lr) * XSTR + lh * 16 + st * 32;
            asm volatile("ldmatrix.sync.aligned.m8n8.x4.shared.b16 {%0,%1,%2,%3}, [%4];"
                         : "=r"(a[fm][0]), "=r"(a[fm][1]), "=r"(a[fm][2]), "=r"(a[fm][3])
                         : "r"(ad));
        }
        uint32_t b[2][4];
#pragma unroll
        for (int np = 0; np < 2; np++) {
            int krw = st * 16 + lr;
            uint32_t bn = (uint32_t)(warp_n + np * 16 + lh * 8) * 2;
            uint32_t bd = SW + krw * 256 + (bn ^ ((krw & 7) << 4));
            asm volatile("ldmatrix.sync.aligned.m8n8.x4.trans.shared.b16 {%0,%1,%2,%3}, [%4];"
                         : "=r"(b[np][0]), "=r"(b[np][1]), "=r"(b[np][2]), "=r"(b[np][3])
                         : "r"(bd));
        }
#pragma unroll
        for (int fm = 0; fm < 4; fm++)
#pragma unroll
            for (int fn = 0; fn < 4; fn++) {
                const int np = fn >> 1, pr = fn & 1;
                asm volatile(
                    "mma.sync.aligned.m16n8k16.row.col.f32.f16.f16.f32 "
                    "{%0,%1,%2,%3}, {%4,%5,%6,%7}, {%8,%9}, {%0,%1,%2,%3};"
                    : "+f"(acc[fm][fn][0]), "+f"(acc[fm][fn][1]),
                      "+f"(acc[fm][fn][2]), "+f"(acc[fm][fn][3])
                    : "r"(a[fm][0]), "r"(a[fm][1]), "r"(a[fm][2]), "r"(a[fm][3]),
                      "r"(b[np][pr * 2]), "r"(b[np][pr * 2 + 1]));
            }
    }
    __syncthreads();                                   // barrier 2 (seal X+W reads)

    // ============ adj panel -> ADJ via cp.async (overlaps epilogue) ============
#pragma unroll
    for (int i = 0; i < 16; i++) {
        int idx = tid + i * 512;                       // 8192 units
        int row = idx >> 5, seg = idx & 31;
        CP_ASYNC16(ADJ + row * ASTR + seg * 16, g_adj16 + row * NN + seg * 8);
    }
    CP_COMMIT();

    // phase-1 epilogue: acc -> SXW (fp16, XOR swizzle)
#pragma unroll
    for (int fm = 0; fm < 4; fm++) {
        const int r0 = warp_m + fm * 16 + grp;
#pragma unroll
        for (int fn = 0; fn < 4; fn++) {
            const int cb = (warp_n + fn * 8 + tg * 2) * 2;
            uint32_t h0 = packh2(acc[fm][fn][0], acc[fm][fn][1]);
            uint32_t h1 = packh2(acc[fm][fn][2], acc[fm][fn][3]);
            asm volatile("st.shared.b32 [%0], %1;"
                         :: "r"(SXW + r0 * 256 + (cb ^ ((r0 & 7) << 4))), "r"(h0) : "memory");
            asm volatile("st.shared.b32 [%0], %1;"
                         :: "r"(SXW + (r0 + 8) * 256 + (cb ^ (((r0 + 8) & 7) << 4))), "r"(h1) : "memory");
        }
    }
    zero_acc();
    CP_WAIT0();
    __syncthreads();                                   // barrier 3

    // ============ phase 2: out = adj @ xw + bias, 16 k16 steps, no barriers ===
#pragma unroll
    for (int st = 0; st < 16; st++) {
        uint32_t a[4][4];
#pragma unroll
        for (int fm = 0; fm < 4; fm++) {
            uint32_t ad = ADJ + (warp_m + fm * 16 + lr) * ASTR + lh * 16 + st * 32;
            asm volatile("ldmatrix.sync.aligned.m8n8.x4.shared.b16 {%0,%1,%2,%3}, [%4];"
                         : "=r"(a[fm][0]), "=r"(a[fm][1]), "=r"(a[fm][2]), "=r"(a[fm][3])
                         : "r"(ad));
        }
        uint32_t b[2][4];
#pragma unroll
        for (int np = 0; np < 2; np++) {
            int krw = st * 16 + lr;
            uint32_t bn = (uint32_t)(warp_n + np * 16 + lh * 8) * 2;
            uint32_t bd = SXW + krw * 256 + (bn ^ ((krw & 7) << 4));
            asm volatile("ldmatrix.sync.aligned.m8n8.x4.trans.shared.b16 {%0,%1,%2,%3}, [%4];"
                         : "=r"(b[np][0]), "=r"(b[np][1]), "=r"(b[np][2]), "=r"(b[np][3])
                         : "r"(bd));
        }
#pragma unroll
        for (int fm = 0; fm < 4; fm++)
#pragma unroll
            for (int fn = 0; fn < 4; fn++) {
                const int np = fn >> 1, pr = fn & 1;
                asm volatile(
                    "mma.sync.aligned.m16n8k16.row.col.f32.f16.f16.f32 "
                    "{%0,%1,%2,%3}, {%4,%5,%6,%7}, {%8,%9}, {%0,%1,%2,%3};"
                    : "+f"(acc[fm][fn][0]), "+f"(acc[fm][fn][1]),
                      "+f"(acc[fm][fn][2]), "+f"(acc[fm][fn][3])
                    : "r"(a[fm][0]), "r"(a[fm][1]), "r"(a[fm][2]), "r"(a[fm][3]),
                      "r"(b[np][pr * 2]), "r"(b[np][pr * 2 + 1]));
            }
    }

    // phase-2 epilogue
#pragma unroll
    for (int fm = 0; fm < 4; fm++) {
        const int r0 = warp_m + fm * 16 + grp;
#pragma unroll
        for (int fn = 0; fn < 4; fn++) {
            const int col = warp_n + fn * 8 + tg * 2;
            float2 b2 = *(const float2*)(bias + col);
            float2 v0 = { acc[fm][fn][0] + b2.x, acc[fm][fn][1] + b2.y };
            float2 v1 = { acc[fm][fn][2] + b2.x, acc[fm][fn][3] + b2.y };
            *(float2*)(out + ((size_t)r0 * NT + t) * NF + col)       = v0;
            *(float2*)(out + ((size_t)(r0 + 8) * NT + t) * NF + col) = v1;
        }
    }
}

// ---------------------------------------------------------------------------
extern "C" void kernel_launch(void* const* d_in, const int* in_sizes, int n_in,
                              void* d_out, int out_size) {
    (void)in_sizes; (void)n_in; (void)out_size;
    const float* node_feats = (const float*)d_in[0];   // [256,2048,128]
    const float* adj        = (const float*)d_in[1];   // [256,256]
    const float* weight     = (const float*)d_in[2];   // [128,128]
    const float* bias       = (const float*)d_in[3];   // [128]
    float* out = (float*)d_out;

    cudaFuncSetAttribute(fused_gcn, cudaFuncAttributeMaxDynamicSharedMemorySize, SMEM_TOT);

    prep_kernel<<<NN, 256>>>(adj);
    fused_gcn<<<NT, 512, SMEM_TOT>>>(node_feats, weight, out, bias);
}

// round 11
// speedup vs baseline: 1.2795x; 1.2795x over previous
#include <cuda_runtime.h>
#include <cuda_fp16.h>
#include <cstdint>

#define NN 256
#define NT 2048
#define NF 128

__device__ __half g_adj16[NN * NN];   // rownorm(adj+I), fp16, [m][k]

__device__ __forceinline__ uint32_t smem_u32(const void* p) {
    uint32_t a;
    asm("{ .reg .u64 t; cvta.to.shared.u64 t, %1; cvt.u32.u64 %0, t; }" : "=r"(a) : "l"(p));
    return a;
}
__device__ __forceinline__ uint32_t packh2(float x, float y) {
    __half2 h = __floats2half2_rn(x, y);
    return *reinterpret_cast<uint32_t*>(&h);
}

// ---------------------------------------------------------------------------
__global__ void prep_kernel(const float* __restrict__ adj) {
    __shared__ float red[256];
    int m = blockIdx.x, j = threadIdx.x;
    float v = adj[m * NN + j] + (j == m ? 1.0f : 0.0f);
    red[j] = v;
    __syncthreads();
#pragma unroll
    for (int off = 128; off > 0; off >>= 1) {
        if (j < off) red[j] += red[j + off];
        __syncthreads();
    }
    g_adj16[m * NN + j] = __float2half_rn(v / red[0]);
}

// ---------------------------------------------------------------------------
// Fused GCN: one CTA per t. 256 threads = 8 warps (4m x 2n), warp tile 64x64
// over the 256x128 output tile; m16n8k16 fp16 mma, fp32 accum.
// Chunked (BK=32) double-buffered A staging with per-chunk barriers (R5 form).
//
// smem (136 KB dynamic):
//   SW  [0,      32768): W fp16, 128 rows x 256B, XOR swizzle
//   SXW [32768,  98304): xw slab fp16, 256 rows x 256B, XOR swizzle
//   STG [98304, 139264): A staging, 2 stages x (256 rows x 80B)
// ---------------------------------------------------------------------------
#define SW_OFF   0
#define SXW_OFF  32768
#define STG_OFF  98304
#define ASTAGE   20480
#define SMEM_TOT 139264

__global__ void __launch_bounds__(256, 1)
fused_gcn(const float* __restrict__ X, const float* __restrict__ W,
          float* __restrict__ out, const float* __restrict__ bias)
{
    extern __shared__ __align__(128) char smem[];
    const uint32_t base = smem_u32(smem);
    const uint32_t SW  = base + SW_OFF;
    const uint32_t SXW = base + SXW_OFF;
    const uint32_t STG = base + STG_OFF;

    const int t    = blockIdx.x;
    const int tid  = threadIdx.x;
    const int warp = tid >> 5;
    const int lane = tid & 31;
    const int lr   = lane & 15, lh = lane >> 4;
    const int grp  = lane >> 2, tg = lane & 3;
    const int warp_m = (warp & 3) * 64;
    const int warp_n = (warp >> 2) * 64;

    float acc[4][8][4];     // 128 regs: 4 fm x 8 fn x 4
    float4 xr[4][2];        // staging transients
    uint4  ar[4];

    auto zero_acc = [&] {
#pragma unroll
        for (int i = 0; i < 4; i++)
#pragma unroll
            for (int j = 0; j < 8; j++)
#pragma unroll
                for (int r = 0; r < 4; r++) acc[i][j][r] = 0.0f;
    };
    auto sts16 = [](uint32_t addr, uint4 v) {
        asm volatile("st.shared.v4.b32 [%0], {%1,%2,%3,%4};"
                     :: "r"(addr), "r"(v.x), "r"(v.y), "r"(v.z), "r"(v.w) : "memory");
    };

    // producers: one BK32 chunk = 1024 x 16B fp16 units; 4 units/thread
    auto loadX = [&](int c) {
#pragma unroll
        for (int i = 0; i < 4; i++) {
            int u = tid + i * 256;
            int row = u >> 2, seg = u & 3;
            const float4* src = (const float4*)(X + ((size_t)row * NT + t) * NF + c * 32 + seg * 8);
            xr[i][0] = src[0];
            xr[i][1] = src[1];
        }
    };
    auto stsX = [&](int s) {
#pragma unroll
        for (int i = 0; i < 4; i++) {
            int u = tid + i * 256;
            int row = u >> 2, seg = u & 3;
            uint4 v;
            v.x = packh2(xr[i][0].x, xr[i][0].y); v.y = packh2(xr[i][0].z, xr[i][0].w);
            v.z = packh2(xr[i][1].x, xr[i][1].y); v.w = packh2(xr[i][1].z, xr[i][1].w);
            sts16(STG + s * ASTAGE + row * 80 + seg * 16, v);
        }
    };
    auto loadAdj = [&](int c) {
#pragma unroll
        for (int i = 0; i < 4; i++) {
            int u = tid + i * 256;
            int row = u >> 2, seg = u & 3;
            ar[i] = *(const uint4*)(g_adj16 + row * NN + c * 32 + seg * 8);
        }
    };
    auto stsAdj = [&](int s) {
#pragma unroll
        for (int i = 0; i < 4; i++) {
            int u = tid + i * 256;
            int row = u >> 2, seg = u & 3;
            sts16(STG + s * ASTAGE + row * 80 + seg * 16, ar[i]);
        }
    };

    // one BK32 chunk of mma: A from staging stage s, B from Bbase (XOR rows)
    auto mma_stage = [&](int c, int s, uint32_t Bbase) {
        const uint32_t ab = STG + s * ASTAGE;
#pragma unroll
        for (int kk = 0; kk < 2; kk++) {
            const int ke = kk * 16;
            uint32_t a[4][4];
#pragma unroll
            for (int fm = 0; fm < 4; fm++) {
                uint32_t ad = ab + (warp_m + fm * 16 + lr) * 80 + lh * 16 + ke * 2;
                asm volatile("ldmatrix.sync.aligned.m8n8.x4.shared.b16 {%0,%1,%2,%3}, [%4];"
                             : "=r"(a[fm][0]), "=r"(a[fm][1]), "=r"(a[fm][2]), "=r"(a[fm][3])
                             : "r"(ad));
            }
            uint32_t b[4][4];
#pragma unroll
            for (int np = 0; np < 4; np++) {
                int krw = c * 32 + ke + lr;
                uint32_t bn = (uint32_t)(warp_n + np * 16 + lh * 8) * 2;
                uint32_t bd = Bbase + krw * 256 + (bn ^ ((krw & 7) << 4));
                asm volatile("ldmatrix.sync.aligned.m8n8.x4.trans.shared.b16 {%0,%1,%2,%3}, [%4];"
                             : "=r"(b[np][0]), "=r"(b[np][1]), "=r"(b[np][2]), "=r"(b[np][3])
                             : "r"(bd));
            }
#pragma unroll
            for (int fm = 0; fm < 4; fm++)
#pragma unroll
                for (int fn = 0; fn < 8; fn++) {
                    const int np = fn >> 1, pr = fn & 1;
                    asm volatile(
                        "mma.sync.aligned.m16n8k16.row.col.f32.f16.f16.f32 "
                        "{%0,%1,%2,%3}, {%4,%5,%6,%7}, {%8,%9}, {%0,%1,%2,%3};"
                        : "+f"(acc[fm][fn][0]), "+f"(acc[fm][fn][1]),
                          "+f"(acc[fm][fn][2]), "+f"(acc[fm][fn][3])
                        : "r"(a[fm][0]), "r"(a[fm][1]), "r"(a[fm][2]), "r"(a[fm][3]),
                          "r"(b[np][pr * 2]), "r"(b[np][pr * 2 + 1]));
                }
        }
    };

    // ---- prologue: W -> SW (swizzled), X chunk 0 -> stage 0 ----
#pragma unroll
    for (int p = 0; p < 8; p++) {
        int u = tid + p * 256;
        int row = u >> 4, seg = u & 15;
        const float4* src = (const float4*)(W + row * NF + seg * 8);
        float4 v0 = src[0], v1 = src[1];
        uint4 w;
        w.x = packh2(v0.x, v0.y); w.y = packh2(v0.z, v0.w);
        w.z = packh2(v1.x, v1.y); w.w = packh2(v1.z, v1.w);
        sts16(SW + row * 256 + ((seg * 16) ^ ((row & 7) << 4)), w);
    }
    loadX(0);
    stsX(0);
    zero_acc();
    __syncthreads();

    // ---- phase 1: xw = X_t @ W (K=128, 4 chunks, double-buffered) ----
#pragma unroll
    for (int c = 0; c < 4; c++) {
        const int s = c & 1;
        if (c < 3) loadX(c + 1);
        mma_stage(c, s, SW);
        if (c < 3) { stsX(s ^ 1); __syncthreads(); }
    }
    __syncthreads();     // seal staging reads before SXW epilogue below? (STG separate; safe)

    // phase-1 epilogue: acc -> SXW (fp16, XOR swizzle)
#pragma unroll
    for (int fm = 0; fm < 4; fm++) {
        const int r0 = warp_m + fm * 16 + grp;
#pragma unroll
        for (int fn = 0; fn < 8; fn++) {
            const int cb = (warp_n + fn * 8 + tg * 2) * 2;
            uint32_t h0 = packh2(acc[fm][fn][0], acc[fm][fn][1]);
            uint32_t h1 = packh2(acc[fm][fn][2], acc[fm][fn][3]);
            asm volatile("st.shared.b32 [%0], %1;"
                         :: "r"(SXW + r0 * 256 + (cb ^ ((r0 & 7) << 4))), "r"(h0) : "memory");
            asm volatile("st.shared.b32 [%0], %1;"
                         :: "r"(SXW + (r0 + 8) * 256 + (cb ^ (((r0 + 8) & 7) << 4))), "r"(h1) : "memory");
        }
    }
    zero_acc();

    // ---- phase 2: out = adj_hat @ xw + bias (K=256, 8 chunks) ----
    loadAdj(0);
    stsAdj(0);
    __syncthreads();
#pragma unroll
    for (int c = 0; c < 8; c++) {
        const int s = c & 1;
        if (c < 7) loadAdj(c + 1);
        mma_stage(c, s, SXW);
        if (c < 7) { stsAdj(s ^ 1); __syncthreads(); }
    }

    // phase-2 epilogue
#pragma unroll
    for (int fm = 0; fm < 4; fm++) {
        const int r0 = warp_m + fm * 16 + grp;
#pragma unroll
        for (int fn = 0; fn < 8; fn++) {
            const int col = warp_n + fn * 8 + tg * 2;
            float2 b2 = *(const float2*)(bias + col);
            float2 v0 = { acc[fm][fn][0] + b2.x, acc[fm][fn][1] + b2.y };
            float2 v1 = { acc[fm][fn][2] + b2.x, acc[fm][fn][3] + b2.y };
            *(float2*)(out + ((size_t)r0 * NT + t) * NF + col)       = v0;
            *(float2*)(out + ((size_t)(r0 + 8) * NT + t) * NF + col) = v1;
        }
    }
}

// ---------------------------------------------------------------------------
extern "C" void kernel_launch(void* const* d_in, const int* in_sizes, int n_in,
                              void* d_out, int out_size) {
    (void)in_sizes; (void)n_in; (void)out_size;
    const float* node_feats = (const float*)d_in[0];   // [256,2048,128]
    const float* adj        = (const float*)d_in[1];   // [256,256]
    const float* weight     = (const float*)d_in[2];   // [128,128]
    const float* bias       = (const float*)d_in[3];   // [128]
    float* out = (float*)d_out;

    cudaFuncSetAttribute(fused_gcn, cudaFuncAttributeMaxDynamicSharedMemorySize, SMEM_TOT);

    prep_kernel<<<NN, 256>>>(adj);
    fused_gcn<<<NT, 256, SMEM_TOT>>>(node_feats, weight, out, bias);
}